// round 1
// baseline (speedup 1.0000x reference)
#include <cuda_runtime.h>

#define N_NODES 100000
#define N_EDGES 1600000
#define SCAN_B  512
#define NB1     ((N_NODES + SCAN_B - 1) / SCAN_B)   // 196

// ---------------- scratch (static device memory; no allocs) ----------------
__device__ float g_bufA[N_NODES * 128];   // h1 / h2 (pre-aggregation GEMM out)
__device__ float g_bufB[N_NODES * 128];   // out1
__device__ float g_bufC[N_NODES * 128];   // s = out2 + out1
__device__ int   g_deg[N_NODES];
__device__ float g_dinv[N_NODES];
__device__ int   g_off[N_NODES];
__device__ int   g_cur[N_NODES];
__device__ int   g_csr_src[N_EDGES];
__device__ float g_csr_w[N_EDGES];
__device__ int   g_bsum[256];

// ---------------- f32x2 packed-FMA helpers (PTX-only on Blackwell) ---------
__device__ __forceinline__ unsigned long long pack2(float a, float b) {
    unsigned long long r;
    asm("mov.b64 %0, {%1, %2};" : "=l"(r) : "f"(a), "f"(b));
    return r;
}
__device__ __forceinline__ void unpack2(float& a, float& b, unsigned long long v) {
    asm("mov.b64 {%0, %1}, %2;" : "=f"(a), "=f"(b) : "l"(v));
}
__device__ __forceinline__ void fma2(unsigned long long& d, unsigned long long a,
                                     unsigned long long b, unsigned long long c) {
    asm("fma.rn.f32x2 %0, %1, %2, %3;" : "=l"(d) : "l"(a), "l"(b), "l"(c));
}

// ---------------- graph preprocessing ----------------
__global__ void k_init() {
    int i = blockIdx.x * blockDim.x + threadIdx.x;
    if (i < N_NODES) g_deg[i] = 1;   // self-loop
}

__global__ void k_count(const int* __restrict__ ei) {
    int e = blockIdx.x * blockDim.x + threadIdx.x;
    if (e < N_EDGES) atomicAdd(&g_deg[ei[N_EDGES + e]], 1);
}

__global__ void k_dinv() {
    int i = blockIdx.x * blockDim.x + threadIdx.x;
    if (i < N_NODES) g_dinv[i] = rsqrtf((float)g_deg[i]);
}

// per-block exclusive scan of (deg-1)
__global__ void k_scan1() {
    __shared__ int sh[SCAN_B];
    int tid = threadIdx.x;
    int i = blockIdx.x * SCAN_B + tid;
    int v = (i < N_NODES) ? (g_deg[i] - 1) : 0;
    sh[tid] = v;
    __syncthreads();
    for (int ofs = 1; ofs < SCAN_B; ofs <<= 1) {
        int t = (tid >= ofs) ? sh[tid - ofs] : 0;
        __syncthreads();
        sh[tid] += t;
        __syncthreads();
    }
    if (i < N_NODES) g_off[i] = sh[tid] - v;       // exclusive within block
    if (tid == SCAN_B - 1) g_bsum[blockIdx.x] = sh[tid];
}

// scan the 196 block sums (single block)
__global__ void k_scan2() {
    __shared__ int sh[256];
    int tid = threadIdx.x;
    int v = (tid < NB1) ? g_bsum[tid] : 0;
    sh[tid] = v;
    __syncthreads();
    for (int ofs = 1; ofs < 256; ofs <<= 1) {
        int t = (tid >= ofs) ? sh[tid - ofs] : 0;
        __syncthreads();
        sh[tid] += t;
        __syncthreads();
    }
    g_bsum[tid] = sh[tid] - v;   // exclusive
}

__global__ void k_scan3() {
    int i = blockIdx.x * blockDim.x + threadIdx.x;
    if (i < N_NODES) {
        int o = g_off[i] + g_bsum[i / SCAN_B];
        g_off[i] = o;
        g_cur[i] = o;
    }
}

__global__ void k_scatter(const int* __restrict__ ei) {
    int e = blockIdx.x * blockDim.x + threadIdx.x;
    if (e < N_EDGES) {
        int s = ei[e];
        int d = ei[N_EDGES + e];
        int p = atomicAdd(&g_cur[d], 1);
        g_csr_src[p] = s;
        g_csr_w[p]   = g_dinv[s] * g_dinv[d];
    }
}

// ---------------- GEMM: C[N,128] = A[N,128] @ W[128,128] (f32x2 packed) ----
__global__ __launch_bounds__(256, 1)
void k_gemm128(const float* __restrict__ A, const float* __restrict__ W,
               float* __restrict__ C) {
    extern __shared__ float sm[];
    float* As = sm;              // [k][m]  (transposed A tile), 128x128
    float* Ws = sm + 128 * 128;  // [k][n], 128x128
    int tid  = threadIdx.x;
    int row0 = blockIdx.x * 128;

    // load W (row-major [k][n]) straight in, 16 float4 per thread
    {
        const float4* Wg  = (const float4*)W;
        float4*       Wsh = (float4*)Ws;
        #pragma unroll
        for (int i = 0; i < 16; i++) Wsh[tid + 256 * i] = Wg[tid + 256 * i];
    }
    // load A tile transposed: thread t handles row t>>1, k-half (t&1)*64
    {
        int r  = tid >> 1;
        int kh = (tid & 1) * 64;
        int gr = row0 + r;
        const float4* Ag = (const float4*)A;
        #pragma unroll
        for (int j = 0; j < 16; j++) {
            int k = kh + j * 4;
            float4 v = make_float4(0.f, 0.f, 0.f, 0.f);
            if (gr < N_NODES) v = Ag[gr * 32 + (k >> 2)];
            As[(k + 0) * 128 + r] = v.x;
            As[(k + 1) * 128 + r] = v.y;
            As[(k + 2) * 128 + r] = v.z;
            As[(k + 3) * 128 + r] = v.w;
        }
    }
    __syncthreads();

    int tx = tid & 15, ty = tid >> 4;    // 8x8 micro-tile per thread
    unsigned long long acc[8][4];
    #pragma unroll
    for (int i = 0; i < 8; i++)
        #pragma unroll
        for (int j = 0; j < 4; j++) acc[i][j] = 0ull;

    #pragma unroll 8
    for (int k = 0; k < 128; k++) {
        float4 a0 = *(const float4*)&As[k * 128 + ty * 8];
        float4 a1 = *(const float4*)&As[k * 128 + ty * 8 + 4];
        const unsigned long long* Bp =
            (const unsigned long long*)&Ws[k * 128 + tx * 8];
        unsigned long long bb0 = Bp[0], bb1 = Bp[1], bb2 = Bp[2], bb3 = Bp[3];
        float av[8] = {a0.x, a0.y, a0.z, a0.w, a1.x, a1.y, a1.z, a1.w};
        #pragma unroll
        for (int i = 0; i < 8; i++) {
            unsigned long long aa = pack2(av[i], av[i]);
            fma2(acc[i][0], aa, bb0, acc[i][0]);
            fma2(acc[i][1], aa, bb1, acc[i][1]);
            fma2(acc[i][2], aa, bb2, acc[i][2]);
            fma2(acc[i][3], aa, bb3, acc[i][3]);
        }
    }

    float4* Cg = (float4*)C;
    #pragma unroll
    for (int i = 0; i < 8; i++) {
        int row = row0 + ty * 8 + i;
        if (row < N_NODES) {
            float4 lo, hi;
            unpack2(lo.x, lo.y, acc[i][0]);
            unpack2(lo.z, lo.w, acc[i][1]);
            unpack2(hi.x, hi.y, acc[i][2]);
            unpack2(hi.z, hi.w, acc[i][3]);
            Cg[row * 32 + tx * 2]     = lo;
            Cg[row * 32 + tx * 2 + 1] = hi;
        }
    }
}

// ---------------- aggregation: one warp per node, float4 per lane ----------
__global__ __launch_bounds__(256)
void k_agg(const float* __restrict__ h, const float* __restrict__ bias,
           const float* __restrict__ prev, float* __restrict__ out,
           int addprev) {
    int warp = threadIdx.x >> 5;
    int lane = threadIdx.x & 31;
    int i = blockIdx.x * 8 + warp;
    if (i >= N_NODES) return;

    const float4* h4 = (const float4*)h;
    float di = g_dinv[i];
    float sl = di * di;                       // self-loop weight
    float4 acc = h4[i * 32 + lane];
    acc.x *= sl; acc.y *= sl; acc.z *= sl; acc.w *= sl;

    int cnt  = g_deg[i] - 1;
    int base = g_off[i];
    int e = 0;
    for (; e + 8 <= cnt; e += 8) {
        int s[8]; float w[8];
        #pragma unroll
        for (int j = 0; j < 8; j++) {
            s[j] = g_csr_src[base + e + j];
            w[j] = g_csr_w[base + e + j];
        }
        float4 v[8];
        #pragma unroll
        for (int j = 0; j < 8; j++) v[j] = h4[s[j] * 32 + lane];
        #pragma unroll
        for (int j = 0; j < 8; j++) {
            acc.x += w[j] * v[j].x; acc.y += w[j] * v[j].y;
            acc.z += w[j] * v[j].z; acc.w += w[j] * v[j].w;
        }
    }
    for (; e < cnt; e++) {
        int   sj = g_csr_src[base + e];
        float wj = g_csr_w[base + e];
        float4 v = h4[sj * 32 + lane];
        acc.x += wj * v.x; acc.y += wj * v.y;
        acc.z += wj * v.z; acc.w += wj * v.w;
    }

    float4 bv = ((const float4*)bias)[lane];
    acc.x = fmaxf(acc.x + bv.x, 0.f);
    acc.y = fmaxf(acc.y + bv.y, 0.f);
    acc.z = fmaxf(acc.z + bv.z, 0.f);
    acc.w = fmaxf(acc.w + bv.w, 0.f);

    if (addprev) {
        float4 p = ((const float4*)prev)[i * 32 + lane];
        acc.x += p.x; acc.y += p.y; acc.z += p.z; acc.w += p.w;
    }
    ((float4*)out)[i * 32 + lane] = acc;
}

// ---------------- classifier GEMM: C[N,40] = S[N,128] @ Wc[128,40] + bc ----
__global__ __launch_bounds__(256, 1)
void k_gemm40(const float* __restrict__ A, const float* __restrict__ W,
              const float* __restrict__ bias, float* __restrict__ C) {
    extern __shared__ float sm[];
    float* As = sm;              // [k][m] 128x128
    float* Ws = sm + 128 * 128;  // [k][40]
    int tid  = threadIdx.x;
    int row0 = blockIdx.x * 128;

    for (int idx = tid; idx < 128 * 40; idx += 256) Ws[idx] = W[idx];
    {
        int r  = tid >> 1;
        int kh = (tid & 1) * 64;
        int gr = row0 + r;
        const float4* Ag = (const float4*)A;
        #pragma unroll
        for (int j = 0; j < 16; j++) {
            int k = kh + j * 4;
            float4 v = make_float4(0.f, 0.f, 0.f, 0.f);
            if (gr < N_NODES) v = Ag[gr * 32 + (k >> 2)];
            As[(k + 0) * 128 + r] = v.x;
            As[(k + 1) * 128 + r] = v.y;
            As[(k + 2) * 128 + r] = v.z;
            As[(k + 3) * 128 + r] = v.w;
        }
    }
    __syncthreads();

    int rg = tid >> 3;          // 32 row groups of 4 rows
    int c0 = (tid & 7) * 5;     // 8 col groups of 5 cols
    float acc[4][5];
    #pragma unroll
    for (int i = 0; i < 4; i++)
        #pragma unroll
        for (int j = 0; j < 5; j++) acc[i][j] = 0.f;

    #pragma unroll 4
    for (int k = 0; k < 128; k++) {
        float4 a = *(const float4*)&As[k * 128 + rg * 4];
        float av[4] = {a.x, a.y, a.z, a.w};
        float bv[5];
        #pragma unroll
        for (int j = 0; j < 5; j++) bv[j] = Ws[k * 40 + c0 + j];
        #pragma unroll
        for (int i = 0; i < 4; i++)
            #pragma unroll
            for (int j = 0; j < 5; j++) acc[i][j] += av[i] * bv[j];
    }

    float bcv[5];
    #pragma unroll
    for (int j = 0; j < 5; j++) bcv[j] = bias[c0 + j];
    #pragma unroll
    for (int i = 0; i < 4; i++) {
        int row = row0 + rg * 4 + i;
        if (row < N_NODES) {
            #pragma unroll
            for (int j = 0; j < 5; j++)
                C[row * 40 + c0 + j] = acc[i][j] + bcv[j];
        }
    }
}

// ---------------- launch ----------------
extern "C" void kernel_launch(void* const* d_in, const int* in_sizes, int n_in,
                              void* d_out, int out_size) {
    const float* x  = (const float*)d_in[0];
    const float* W1 = (const float*)d_in[1];
    const float* b1 = (const float*)d_in[2];
    const float* W2 = (const float*)d_in[3];
    const float* b2 = (const float*)d_in[4];
    const float* Wc = (const float*)d_in[5];
    const float* bc = (const float*)d_in[6];
    const int*   ei = (const int*)d_in[7];
    float* out = (float*)d_out;

    const int SMEM_G128 = 2 * 128 * 128 * 4;                  // 128 KB
    const int SMEM_G40  = 128 * 128 * 4 + 128 * 40 * 4;       // 84.5 KB
    cudaFuncSetAttribute(k_gemm128, cudaFuncAttributeMaxDynamicSharedMemorySize, SMEM_G128);
    cudaFuncSetAttribute(k_gemm40,  cudaFuncAttributeMaxDynamicSharedMemorySize, SMEM_G40);

    float *pA, *pB, *pC;
    cudaGetSymbolAddress((void**)&pA, g_bufA);
    cudaGetSymbolAddress((void**)&pB, g_bufB);
    cudaGetSymbolAddress((void**)&pC, g_bufC);

    const int GN  = (N_NODES + 255) / 256;   // 391
    const int GE  = (N_EDGES + 255) / 256;   // 6250
    const int GT  = (N_NODES + 127) / 128;   // 782
    const int GAG = (N_NODES + 7) / 8;       // 12500

    // graph preprocessing (rebuilt every replay; deterministic work)
    k_init<<<GN, 256>>>();
    k_count<<<GE, 256>>>(ei);
    k_dinv<<<GN, 256>>>();
    k_scan1<<<NB1, SCAN_B>>>();
    k_scan2<<<1, 256>>>();
    k_scan3<<<GN, 256>>>();
    k_scatter<<<GE, 256>>>(ei);

    // layer 1
    k_gemm128<<<GT, 256, SMEM_G128>>>(x, W1, pA);
    k_agg<<<GAG, 256>>>(pA, b1, nullptr, pB, 0);
    // layer 2
    k_gemm128<<<GT, 256, SMEM_G128>>>(pB, W2, pA);
    k_agg<<<GAG, 256>>>(pA, b2, pB, pC, 1);
    // classifier
    k_gemm40<<<GT, 256, SMEM_G40>>>(pC, Wc, bc, out);
}